// round 1
// baseline (speedup 1.0000x reference)
#include <cuda_runtime.h>
#include <cuda_bf16.h>

#define FEAT_N 2
#define FEAT_C 512
#define FEAT_H 100
#define FEAT_W 152
#define NUM_ROIS 512
#define AH 14
#define AW 14
#define SPATIAL_SCALE 0.0625f
#define CH_CHUNK 8          // channels per block
#define CHUNKS_PER_ROI (FEAT_C / CH_CHUNK)   // 64
#define BINS (AH * AW)      // 196

__global__ __launch_bounds__(BINS) void roi_align_kernel(
    const float* __restrict__ feat,
    const float* __restrict__ rois,
    float* __restrict__ out)
{
    // blockIdx.x = r * CHUNKS_PER_ROI + chunk
    const int r      = blockIdx.x >> 6;          // / 64
    const int chunk  = blockIdx.x & 63;
    const int c0     = chunk * CH_CHUNK;

    const int tid = threadIdx.x;                 // 0..195
    const int ph  = tid / AW;
    const int pw  = tid - ph * AW;

    // roi params (broadcast loads, L1-hit after first block per roi)
    const float* rp = rois + r * 5;
    const int   b       = (int)rp[0];
    const float x_start = rp[1] * SPATIAL_SCALE;
    const float y_start = rp[2] * SPATIAL_SCALE;
    const float x_end   = rp[3] * SPATIAL_SCALE;
    const float y_end   = rp[4] * SPATIAL_SCALE;

    const float roi_w = fmaxf(x_end - x_start, 0.0f);
    const float roi_h = fmaxf(y_end - y_start, 0.0f);
    const float bin_h = roi_h / (float)(AH - 1);
    const float bin_w = roi_w / (float)(AW - 1);

    float ys = y_start + (float)ph * bin_h;
    float xs = x_start + (float)pw * bin_w;
    ys = fminf(fmaxf(ys, 0.0f), (float)(FEAT_H - 1));
    xs = fminf(fmaxf(xs, 0.0f), (float)(FEAT_W - 1));

    const int y0 = (int)floorf(ys);
    const int x0 = (int)floorf(xs);
    const int y1 = min(y0 + 1, FEAT_H - 1);
    const int x1 = min(x0 + 1, FEAT_W - 1);
    const float wy = ys - (float)y0;
    const float wx = xs - (float)x0;

    const float w00 = (1.0f - wy) * (1.0f - wx);
    const float w01 = (1.0f - wy) * wx;
    const float w10 = wy * (1.0f - wx);
    const float w11 = wy * wx;

    const int o00 = y0 * FEAT_W + x0;
    const int o01 = y0 * FEAT_W + x1;
    const int o10 = y1 * FEAT_W + x0;
    const int o11 = y1 * FEAT_W + x1;

    const int HW = FEAT_H * FEAT_W;
    const float* f = feat + ((size_t)b * FEAT_C + c0) * HW;
    float* op = out + ((size_t)r * FEAT_C + c0) * BINS + tid;

    #pragma unroll
    for (int cc = 0; cc < CH_CHUNK; cc++) {
        const float* fp = f + cc * HW;
        float v = w00 * __ldg(fp + o00)
                + w01 * __ldg(fp + o01)
                + w10 * __ldg(fp + o10)
                + w11 * __ldg(fp + o11);
        op[cc * BINS] = v;
    }
}

extern "C" void kernel_launch(void* const* d_in, const int* in_sizes, int n_in,
                              void* d_out, int out_size)
{
    const float* feat = (const float*)d_in[0];
    const float* rois = (const float*)d_in[1];
    float* out = (float*)d_out;

    dim3 grid(NUM_ROIS * CHUNKS_PER_ROI);
    dim3 block(BINS);
    roi_align_kernel<<<grid, block>>>(feat, rois, out);
}